// round 4
// baseline (speedup 1.0000x reference)
#include <cuda_runtime.h>
#include <cstdint>

#define D_MODEL 1024
#define NHEAD   16
#define HDIM    64
#define BATCH   2
#define SEQ     2048
#define MROWS   (BATCH*SEQ)       // 4096
#define QKVDIM  (3*D_MODEL)       // 3072

// Scratch (no cudaMalloc allowed)
__device__ float g_qkv [BATCH*SEQ*QKVDIM];   // 50 MB
__device__ float g_attn[BATCH*SEQ*D_MODEL];  // 16 MB

// ---------------------------------------------------------------------------
// helpers
// ---------------------------------------------------------------------------
static __device__ __forceinline__ uint32_t f2tf(float x) {
    uint32_t t;
    asm("cvt.rna.tf32.f32 %0, %1;" : "=r"(t) : "f"(x));
    return t;
}
static __device__ __forceinline__ float f2tff(float x) {
    return __uint_as_float(f2tf(x));
}
// D = A(16x8) * B(8x8) + D, tf32 inputs, fp32 accum
static __device__ __forceinline__ void mma8(
    float& c0, float& c1, float& c2, float& c3,
    uint32_t a0, uint32_t a1, uint32_t a2, uint32_t a3,
    uint32_t b0, uint32_t b1)
{
    asm volatile(
        "mma.sync.aligned.m16n8k8.row.col.f32.tf32.tf32.f32 "
        "{%0,%1,%2,%3}, {%4,%5,%6,%7}, {%8,%9}, {%0,%1,%2,%3};"
        : "+f"(c0), "+f"(c1), "+f"(c2), "+f"(c3)
        : "r"(a0), "r"(a1), "r"(a2), "r"(a3), "r"(b0), "r"(b1));
}

// ===========================================================================
// tf32 mma GEMM (TN):  C[m][n] = sum_k A[m*K+k] * B[n*K+k]
// BM=BN=128, BK=32, 512 thr, 16 warps (4m x 4n), warp tile 32x32.
// Smem word layout: tile[m][k] at  m*32 + (k ^ ((m&7)<<2))  -> conflict-free.
// __launch_bounds__(512,2): 2 CTAs/SM (32 warps) for latency hiding.
// ===========================================================================
#define GEMM_SMEM 65536   // 2 stages x (A 4096 + B 4096 words) x 4B

static __device__ __forceinline__ int swz(int m, int k) {
    return m * 32 + (k ^ ((m & 7) << 2));
}

__global__ void __launch_bounds__(512, 2) gemm_tf32(
    const float* __restrict__ A, const float* __restrict__ B,
    float* __restrict__ C, int M, int N, int K)
{
    extern __shared__ float smg[];

    const int tid  = threadIdx.x;
    const int wid  = tid >> 5;
    const int lane = tid & 31;
    const int g    = lane >> 2;     // groupID 0..7
    const int ct   = lane & 3;      // ctid 0..3
    const int wm   = wid & 3;       // warp m slice (x32)
    const int wn   = wid >> 2;      // warp n slice (x32)
    const int bm   = blockIdx.y * 128;
    const int bn   = blockIdx.x * 128;

    // gmem load mapping: 512 thr, each loads 8 floats (2 float4) of A and B
    const int row  = tid >> 2;      // 0..127
    const int qk   = (tid & 3) * 8; // k offset 0,8,16,24
    const float* Ap = A + (size_t)(bm + row) * K + qk;
    const float* Bp = B + (size_t)(bn + row) * K + qk;
    const int nkt = K / 32;

    float acc[2][4][4];
    #pragma unroll
    for (int i = 0; i < 2; i++)
        #pragma unroll
        for (int j = 0; j < 4; j++)
            #pragma unroll
            for (int e = 0; e < 4; e++) acc[i][j][e] = 0.f;

    float4 av[2], bv[2];
    // prologue: tile 0
    #pragma unroll
    for (int i = 0; i < 2; i++) {
        av[i] = *(const float4*)(Ap + i * 4);
        bv[i] = *(const float4*)(Bp + i * 4);
    }
    {
        float* As = smg;
        float* Bs = smg + 4096;
        #pragma unroll
        for (int i = 0; i < 2; i++) {
            int k = qk + i * 4;
            *(float4*)&As[swz(row, k)] = make_float4(
                f2tff(av[i].x), f2tff(av[i].y), f2tff(av[i].z), f2tff(av[i].w));
            *(float4*)&Bs[swz(row, k)] = make_float4(
                f2tff(bv[i].x), f2tff(bv[i].y), f2tff(bv[i].z), f2tff(bv[i].w));
        }
    }
    __syncthreads();

    for (int kt = 0; kt < nkt; kt++) {
        const uint32_t* As = (const uint32_t*)(smg + (kt & 1) * 8192);
        const uint32_t* Bs = As + 4096;

        if (kt + 1 < nkt) {
            const float* Ap2 = Ap + (kt + 1) * 32;
            const float* Bp2 = Bp + (kt + 1) * 32;
            #pragma unroll
            for (int i = 0; i < 2; i++) {
                av[i] = *(const float4*)(Ap2 + i * 4);
                bv[i] = *(const float4*)(Bp2 + i * 4);
            }
        }

        #pragma unroll
        for (int ks = 0; ks < 4; ks++) {
            uint32_t a[2][4];
            #pragma unroll
            for (int mi = 0; mi < 2; mi++) {
                int m0 = wm * 32 + mi * 16 + g;
                a[mi][0] = As[swz(m0,     ks * 8 + ct)];
                a[mi][1] = As[swz(m0 + 8, ks * 8 + ct)];
                a[mi][2] = As[swz(m0,     ks * 8 + ct + 4)];
                a[mi][3] = As[swz(m0 + 8, ks * 8 + ct + 4)];
            }
            uint32_t bb[4][2];
            #pragma unroll
            for (int nt = 0; nt < 4; nt++) {
                int n0 = wn * 32 + nt * 8 + g;
                bb[nt][0] = Bs[swz(n0, ks * 8 + ct)];
                bb[nt][1] = Bs[swz(n0, ks * 8 + ct + 4)];
            }
            #pragma unroll
            for (int mi = 0; mi < 2; mi++)
                #pragma unroll
                for (int nt = 0; nt < 4; nt++)
                    mma8(acc[mi][nt][0], acc[mi][nt][1], acc[mi][nt][2], acc[mi][nt][3],
                         a[mi][0], a[mi][1], a[mi][2], a[mi][3],
                         bb[nt][0], bb[nt][1]);
        }

        if (kt + 1 < nkt) {
            __syncthreads();
            float* As2 = smg + ((kt + 1) & 1) * 8192;
            float* Bs2 = As2 + 4096;
            #pragma unroll
            for (int i = 0; i < 2; i++) {
                int k = qk + i * 4;
                *(float4*)&As2[swz(row, k)] = make_float4(
                    f2tff(av[i].x), f2tff(av[i].y), f2tff(av[i].z), f2tff(av[i].w));
                *(float4*)&Bs2[swz(row, k)] = make_float4(
                    f2tff(bv[i].x), f2tff(bv[i].y), f2tff(bv[i].z), f2tff(bv[i].w));
            }
            __syncthreads();
        }
    }

    // epilogue: direct float2 stores
    #pragma unroll
    for (int mi = 0; mi < 2; mi++) {
        int r0 = bm + wm * 32 + mi * 16 + g;
        #pragma unroll
        for (int nt = 0; nt < 4; nt++) {
            int c0 = bn + wn * 32 + nt * 8 + 2 * ct;
            *(float2*)&C[(size_t)r0 * N + c0]       = make_float2(acc[mi][nt][0], acc[mi][nt][1]);
            *(float2*)&C[(size_t)(r0 + 8) * N + c0] = make_float2(acc[mi][nt][2], acc[mi][nt][3]);
        }
    }
}

// ===========================================================================
// Flash attention, tf32 mma (unchanged from round 3).
// ===========================================================================
#define LDQ 68
#define LDK 68
#define LDV 72
#define LDP 68
#define QS_W   (128*LDQ)
#define KS_W   (64*LDK)
#define VS_W   (64*LDV)
#define PS_W   (128*LDP)
#define ATTN_SMEM ((QS_W+KS_W+VS_W+PS_W)*4)   // 105472 B

__global__ void __launch_bounds__(256) attn_mma(
    const float* __restrict__ qkv, float* __restrict__ attn_out)
{
    extern __shared__ float sm[];
    float* Qs = sm;
    float* Ks = Qs + QS_W;
    float* Vs = Ks + KS_W;
    float* Ps = Vs + VS_W;
    const uint32_t* Qu = (const uint32_t*)Qs;
    const uint32_t* Ku = (const uint32_t*)Ks;
    const uint32_t* Vu = (const uint32_t*)Vs;
    const uint32_t* Pu = (const uint32_t*)Ps;

    const int qt  = (int)gridDim.x - 1 - (int)blockIdx.x;
    const int h   = blockIdx.y;
    const int b   = blockIdx.z;
    const int tid = threadIdx.x;
    const int wid = tid >> 5;
    const int lane = tid & 31;
    const int g   = lane >> 2;
    const int ct  = lane & 3;
    const int q0  = qt * 128;
    const int rl  = wid * 16 + g;

    const size_t rs = QKVDIM;
    const float* Qg = qkv + (size_t)b * SEQ * rs + h * HDIM;
    const float* Kg = Qg + D_MODEL;
    const float* Vg = Qg + 2 * D_MODEL;

    #pragma unroll
    for (int it = 0; it < 8; it++) {
        int idx = tid + it * 256;
        int row = idx >> 4;
        int d0  = (idx & 15) << 2;
        float4 q4 = *(const float4*)(Qg + (size_t)(q0 + row) * rs + d0);
        *(float4*)&Qs[row * LDQ + d0] = make_float4(
            f2tff(q4.x * 0.125f), f2tff(q4.y * 0.125f),
            f2tff(q4.z * 0.125f), f2tff(q4.w * 0.125f));
    }

    float m_lo = -1e30f, m_hi = -1e30f, l_lo = 0.f, l_hi = 0.f;
    float o[8][4];
    #pragma unroll
    for (int nt = 0; nt < 8; nt++)
        #pragma unroll
        for (int e = 0; e < 4; e++) o[nt][e] = 0.f;

    const int nkt = 2 * qt + 2;
    for (int kt = 0; kt < nkt; kt++) {
        const int k0 = kt * 64;
        __syncthreads();
        #pragma unroll
        for (int it = 0; it < 4; it++) {
            int idx = tid + it * 256;
            int row = idx >> 4;
            int d0  = (idx & 15) << 2;
            float4 k4 = *(const float4*)(Kg + (size_t)(k0 + row) * rs + d0);
            *(float4*)&Ks[row * LDK + d0] = make_float4(
                f2tff(k4.x), f2tff(k4.y), f2tff(k4.z), f2tff(k4.w));
            float4 v4 = *(const float4*)(Vg + (size_t)(k0 + row) * rs + d0);
            *(float4*)&Vs[row * LDV + d0] = make_float4(
                f2tff(v4.x), f2tff(v4.y), f2tff(v4.z), f2tff(v4.w));
        }
        __syncthreads();

        if (k0 > q0 + wid * 16 + 15) continue;

        float s[8][4];
        #pragma unroll
        for (int nt = 0; nt < 8; nt++)
            #pragma unroll
            for (int e = 0; e < 4; e++) s[nt][e] = 0.f;

        #pragma unroll
        for (int ks = 0; ks < 8; ks++) {
            uint32_t a0 = Qu[rl * LDQ + ks * 8 + ct];
            uint32_t a1 = Qu[(rl + 8) * LDQ + ks * 8 + ct];
            uint32_t a2 = Qu[rl * LDQ + ks * 8 + ct + 4];
            uint32_t a3 = Qu[(rl + 8) * LDQ + ks * 8 + ct + 4];
            #pragma unroll
            for (int nt = 0; nt < 8; nt++) {
                uint32_t b0 = Ku[(nt * 8 + g) * LDK + ks * 8 + ct];
                uint32_t b1 = Ku[(nt * 8 + g) * LDK + ks * 8 + ct + 4];
                mma8(s[nt][0], s[nt][1], s[nt][2], s[nt][3], a0, a1, a2, a3, b0, b1);
            }
        }

        const int rglo = q0 + rl;
        const int rghi = rglo + 8;
        if (k0 + 63 > rglo) {
            #pragma unroll
            for (int nt = 0; nt < 8; nt++) {
                int key = k0 + nt * 8 + 2 * ct;
                if (key     > rglo) s[nt][0] = -1e30f;
                if (key + 1 > rglo) s[nt][1] = -1e30f;
                if (key     > rghi) s[nt][2] = -1e30f;
                if (key + 1 > rghi) s[nt][3] = -1e30f;
            }
        }

        float tlo = -1e30f, thi = -1e30f;
        #pragma unroll
        for (int nt = 0; nt < 8; nt++) {
            tlo = fmaxf(tlo, fmaxf(s[nt][0], s[nt][1]));
            thi = fmaxf(thi, fmaxf(s[nt][2], s[nt][3]));
        }
        tlo = fmaxf(tlo, __shfl_xor_sync(0xffffffffu, tlo, 1));
        tlo = fmaxf(tlo, __shfl_xor_sync(0xffffffffu, tlo, 2));
        thi = fmaxf(thi, __shfl_xor_sync(0xffffffffu, thi, 1));
        thi = fmaxf(thi, __shfl_xor_sync(0xffffffffu, thi, 2));

        float mn_lo = fmaxf(m_lo, tlo);
        float mn_hi = fmaxf(m_hi, thi);
        float al_lo = __expf(m_lo - mn_lo);
        float al_hi = __expf(m_hi - mn_hi);
        m_lo = mn_lo; m_hi = mn_hi;

        float ps_lo = 0.f, ps_hi = 0.f;
        #pragma unroll
        for (int nt = 0; nt < 8; nt++) {
            float p0 = __expf(s[nt][0] - mn_lo);
            float p1 = __expf(s[nt][1] - mn_lo);
            float p2 = __expf(s[nt][2] - mn_hi);
            float p3 = __expf(s[nt][3] - mn_hi);
            ps_lo += p0 + p1;
            ps_hi += p2 + p3;
            int col = nt * 8 + 2 * ct;
            *(float2*)&Ps[rl * LDP + col]       = make_float2(f2tff(p0), f2tff(p1));
            *(float2*)&Ps[(rl + 8) * LDP + col] = make_float2(f2tff(p2), f2tff(p3));
        }
        ps_lo += __shfl_xor_sync(0xffffffffu, ps_lo, 1);
        ps_lo += __shfl_xor_sync(0xffffffffu, ps_lo, 2);
        ps_hi += __shfl_xor_sync(0xffffffffu, ps_hi, 1);
        ps_hi += __shfl_xor_sync(0xffffffffu, ps_hi, 2);
        l_lo = l_lo * al_lo + ps_lo;
        l_hi = l_hi * al_hi + ps_hi;

        #pragma unroll
        for (int nt = 0; nt < 8; nt++) {
            o[nt][0] *= al_lo; o[nt][1] *= al_lo;
            o[nt][2] *= al_hi; o[nt][3] *= al_hi;
        }
        __syncwarp();

        #pragma unroll
        for (int ks = 0; ks < 8; ks++) {
            uint32_t a0 = Pu[rl * LDP + ks * 8 + ct];
            uint32_t a1 = Pu[(rl + 8) * LDP + ks * 8 + ct];
            uint32_t a2 = Pu[rl * LDP + ks * 8 + ct + 4];
            uint32_t a3 = Pu[(rl + 8) * LDP + ks * 8 + ct + 4];
            #pragma unroll
            for (int nt = 0; nt < 8; nt++) {
                uint32_t b0 = Vu[(ks * 8 + ct) * LDV + nt * 8 + g];
                uint32_t b1 = Vu[(ks * 8 + ct + 4) * LDV + nt * 8 + g];
                mma8(o[nt][0], o[nt][1], o[nt][2], o[nt][3], a0, a1, a2, a3, b0, b1);
            }
        }
    }

    float inv_lo = 1.0f / l_lo;
    float inv_hi = 1.0f / l_hi;
    float* Og = attn_out + (size_t)(b * SEQ + q0) * D_MODEL + h * HDIM;
    #pragma unroll
    for (int nt = 0; nt < 8; nt++) {
        int col = nt * 8 + 2 * ct;
        *(float2*)&Og[(size_t)rl * D_MODEL + col] =
            make_float2(o[nt][0] * inv_lo, o[nt][1] * inv_lo);
        *(float2*)&Og[(size_t)(rl + 8) * D_MODEL + col] =
            make_float2(o[nt][2] * inv_hi, o[nt][3] * inv_hi);
    }
}

// ===========================================================================
extern "C" void kernel_launch(void* const* d_in, const int* in_sizes, int n_in,
                              void* d_out, int out_size)
{
    const float* x      = (const float*)d_in[0];
    const float* w_qkv  = (const float*)d_in[1];
    const float* w_proj = (const float*)d_in[2];
    float* out = (float*)d_out;

    float *qkv, *attn;
    cudaGetSymbolAddress((void**)&qkv,  g_qkv);
    cudaGetSymbolAddress((void**)&attn, g_attn);

    cudaFuncSetAttribute(gemm_tf32,
                         cudaFuncAttributeMaxDynamicSharedMemorySize, GEMM_SMEM);
    cudaFuncSetAttribute(attn_mma,
                         cudaFuncAttributeMaxDynamicSharedMemorySize, ATTN_SMEM);

    // 1) QKV projection
    dim3 g1(QKVDIM/128, MROWS/128);
    gemm_tf32<<<g1, 512, GEMM_SMEM>>>(x, w_qkv, qkv, MROWS, QKVDIM, D_MODEL);

    // 2) causal flash attention (tf32 mma)
    dim3 g2(SEQ/128, NHEAD, BATCH);
    attn_mma<<<g2, 256, ATTN_SMEM>>>(qkv, attn);

    // 3) output projection
    dim3 g3(D_MODEL/128, MROWS/128);
    gemm_tf32<<<g3, 512, GEMM_SMEM>>>(attn, w_proj, out, MROWS, D_MODEL, D_MODEL);
}

// round 5
// speedup vs baseline: 1.4373x; 1.4373x over previous
#include <cuda_runtime.h>
#include <cstdint>

#define D_MODEL 1024
#define NHEAD   16
#define HDIM    64
#define BATCH   2
#define SEQ     2048
#define MROWS   (BATCH*SEQ)       // 4096
#define QKVDIM  (3*D_MODEL)       // 3072

// Scratch (no cudaMalloc allowed)
__device__ float g_qkv [BATCH*SEQ*QKVDIM];   // 50 MB
__device__ float g_attn[BATCH*SEQ*D_MODEL];  // 16 MB

// ---------------------------------------------------------------------------
// helpers
// ---------------------------------------------------------------------------
static __device__ __forceinline__ uint32_t smem_u32(const void* p) {
    uint32_t a;
    asm("{ .reg .u64 t; cvta.to.shared.u64 t, %1; cvt.u32.u64 %0, t; }"
        : "=r"(a) : "l"(p));
    return a;
}
static __device__ __forceinline__ float f2tff(float x) {
    uint32_t t;
    asm("cvt.rna.tf32.f32 %0, %1;" : "=r"(t) : "f"(x));
    return __uint_as_float(t);
}
// D = A(16x8) * B(8x8) + D, tf32 inputs, fp32 accum
static __device__ __forceinline__ void mma8(
    float& c0, float& c1, float& c2, float& c3,
    uint32_t a0, uint32_t a1, uint32_t a2, uint32_t a3,
    uint32_t b0, uint32_t b1)
{
    asm volatile(
        "mma.sync.aligned.m16n8k8.row.col.f32.tf32.tf32.f32 "
        "{%0,%1,%2,%3}, {%4,%5,%6,%7}, {%8,%9}, {%0,%1,%2,%3};"
        : "+f"(c0), "+f"(c1), "+f"(c2), "+f"(c3)
        : "r"(a0), "r"(a1), "r"(a2), "r"(a3), "r"(b0), "r"(b1));
}
static __device__ __forceinline__ void ldmx4(
    uint32_t& r0, uint32_t& r1, uint32_t& r2, uint32_t& r3, uint32_t addr)
{
    asm volatile("ldmatrix.sync.aligned.m8n8.x4.shared.b16 {%0,%1,%2,%3}, [%4];"
                 : "=r"(r0), "=r"(r1), "=r"(r2), "=r"(r3) : "r"(addr));
}

// ===========================================================================
// tf32 mma GEMM (TN):  C[m][n] = sum_k A[m*K+k] * B[n*K+k]
// BM=BN=128, BK=32, 512 thr, 16 warps (4m x 4n), warp tile 32x32.
// Smem word layout: tile[m][k] at m*32 + (k ^ ((m&7)<<2)); fragments loaded
// with ldmatrix.x4 (conflict-free). Single __syncthreads per k-tile.
// ===========================================================================
#define GEMM_SMEM 65536   // 2 stages x (A 4096 + B 4096 words) x 4B

static __device__ __forceinline__ int swz(int m, int k) {
    return m * 32 + (k ^ ((m & 7) << 2));
}

__global__ void __launch_bounds__(512, 1) gemm_tf32(
    const float* __restrict__ A, const float* __restrict__ B,
    float* __restrict__ C, int M, int N, int K)
{
    extern __shared__ float smg[];
    const uint32_t sbase = smem_u32(smg);

    const int tid  = threadIdx.x;
    const int wid  = tid >> 5;
    const int lane = tid & 31;
    const int g    = lane >> 2;
    const int ct   = lane & 3;
    const int wm   = wid & 3;       // warp m slice (x32)
    const int wn   = wid >> 2;      // warp n slice (x32)
    const int bm   = blockIdx.y * 128;
    const int bn   = blockIdx.x * 128;

    // ldmatrix lane mapping
    const int l8  = lane & 7;
    const int sel = lane >> 3;                 // 0..3
    const uint32_t xv = (uint32_t)(l8 << 2);
    const int arow0 = wm * 32 + l8 + ((sel & 1) << 3);
    const int kca   = (sel >> 1) << 2;
    const int brow0 = wn * 32 + l8 + ((sel >> 1) << 3);
    const int kcb   = (sel & 1) << 2;

    uint32_t aoff[2], boff[2], kofa[4], kofb[4];
    #pragma unroll
    for (int mi = 0; mi < 2; mi++) aoff[mi] = (uint32_t)((arow0 + mi * 16) * 128);
    #pragma unroll
    for (int p = 0; p < 2; p++)  boff[p]  = 16384u + (uint32_t)((brow0 + p * 16) * 128);
    #pragma unroll
    for (int ks = 0; ks < 4; ks++) {
        kofa[ks] = (uint32_t)(((ks * 8 + kca) ^ (int)xv) << 2);
        kofb[ks] = (uint32_t)(((ks * 8 + kcb) ^ (int)xv) << 2);
    }

    // gmem load mapping: 512 thr, each loads 8 floats (2 float4) of A and B
    const int row = tid >> 2;       // 0..127
    const int qk  = (tid & 3) * 8;  // k offset 0,8,16,24
    const float* Ap = A + (size_t)(bm + row) * K + qk;
    const float* Bp = B + (size_t)(bn + row) * K + qk;
    const int nkt = K / 32;

    float acc[2][4][4];
    #pragma unroll
    for (int i = 0; i < 2; i++)
        #pragma unroll
        for (int j = 0; j < 4; j++)
            #pragma unroll
            for (int e = 0; e < 4; e++) acc[i][j][e] = 0.f;

    float4 av[2], bv[2];
    // prologue: tile 0 -> buf 0
    #pragma unroll
    for (int i = 0; i < 2; i++) {
        av[i] = *(const float4*)(Ap + i * 4);
        bv[i] = *(const float4*)(Bp + i * 4);
    }
    {
        float* As = smg;
        float* Bs = smg + 4096;
        #pragma unroll
        for (int i = 0; i < 2; i++) {
            int k = qk + i * 4;
            *(float4*)&As[swz(row, k)] = make_float4(
                f2tff(av[i].x), f2tff(av[i].y), f2tff(av[i].z), f2tff(av[i].w));
            *(float4*)&Bs[swz(row, k)] = make_float4(
                f2tff(bv[i].x), f2tff(bv[i].y), f2tff(bv[i].z), f2tff(bv[i].w));
        }
    }
    __syncthreads();

    for (int kt = 0; kt < nkt; kt++) {
        const uint32_t cbase = sbase + (uint32_t)(kt & 1) * 32768u;

        if (kt + 1 < nkt) {
            const float* Ap2 = Ap + (kt + 1) * 32;
            const float* Bp2 = Bp + (kt + 1) * 32;
            #pragma unroll
            for (int i = 0; i < 2; i++) {
                av[i] = *(const float4*)(Ap2 + i * 4);
                bv[i] = *(const float4*)(Bp2 + i * 4);
            }
        }

        #pragma unroll
        for (int ks = 0; ks < 4; ks++) {
            uint32_t a[2][4], bb[2][4];
            #pragma unroll
            for (int mi = 0; mi < 2; mi++)
                ldmx4(a[mi][0], a[mi][1], a[mi][2], a[mi][3],
                      cbase + aoff[mi] + kofa[ks]);
            #pragma unroll
            for (int p = 0; p < 2; p++)
                ldmx4(bb[p][0], bb[p][1], bb[p][2], bb[p][3],
                      cbase + boff[p] + kofb[ks]);
            #pragma unroll
            for (int mi = 0; mi < 2; mi++)
                #pragma unroll
                for (int nt = 0; nt < 4; nt++)
                    mma8(acc[mi][nt][0], acc[mi][nt][1], acc[mi][nt][2], acc[mi][nt][3],
                         a[mi][0], a[mi][1], a[mi][2], a[mi][3],
                         bb[nt >> 1][(nt & 1) * 2], bb[nt >> 1][(nt & 1) * 2 + 1]);
        }

        if (kt + 1 < nkt) {
            float* As2 = smg + ((kt + 1) & 1) * 8192;
            float* Bs2 = As2 + 4096;
            #pragma unroll
            for (int i = 0; i < 2; i++) {
                int k = qk + i * 4;
                *(float4*)&As2[swz(row, k)] = make_float4(
                    f2tff(av[i].x), f2tff(av[i].y), f2tff(av[i].z), f2tff(av[i].w));
                *(float4*)&Bs2[swz(row, k)] = make_float4(
                    f2tff(bv[i].x), f2tff(bv[i].y), f2tff(bv[i].z), f2tff(bv[i].w));
            }
        }
        __syncthreads();
    }

    // epilogue: direct float2 stores
    #pragma unroll
    for (int mi = 0; mi < 2; mi++) {
        int r0 = bm + wm * 32 + mi * 16 + g;
        #pragma unroll
        for (int nt = 0; nt < 4; nt++) {
            int c0 = bn + wn * 32 + nt * 8 + 2 * ct;
            *(float2*)&C[(size_t)r0 * N + c0]       = make_float2(acc[mi][nt][0], acc[mi][nt][1]);
            *(float2*)&C[(size_t)(r0 + 8) * N + c0] = make_float2(acc[mi][nt][2], acc[mi][nt][3]);
        }
    }
}

// ===========================================================================
// Flash attention, tf32 mma + ldmatrix fragment loads.
// Q tile 128, K/V tile 64; 8 warps, warp w owns rows [w*16, w*16+16).
// Q/K/P frags via ldmatrix (padded stride 68 -> conflict-free); V scalar.
// ===========================================================================
#define LDQ 68
#define LDK 68
#define LDV 72
#define LDP 68
#define QS_W   (128*LDQ)
#define KS_W   (64*LDK)
#define VS_W   (64*LDV)
#define PS_W   (128*LDP)
#define ATTN_SMEM ((QS_W+KS_W+VS_W+PS_W)*4)   // 105472 B

__global__ void __launch_bounds__(256) attn_mma(
    const float* __restrict__ qkv, float* __restrict__ attn_out)
{
    extern __shared__ float sm[];
    float* Qs = sm;
    float* Ks = Qs + QS_W;
    float* Vs = Ks + KS_W;
    float* Ps = Vs + VS_W;
    const uint32_t* Vu = (const uint32_t*)Vs;

    const int qt  = (int)gridDim.x - 1 - (int)blockIdx.x;
    const int h   = blockIdx.y;
    const int b   = blockIdx.z;
    const int tid = threadIdx.x;
    const int wid = tid >> 5;
    const int lane = tid & 31;
    const int g   = lane >> 2;
    const int ct  = lane & 3;
    const int q0  = qt * 128;
    const int rl  = wid * 16 + g;

    // ldmatrix lane mapping
    const int l8  = lane & 7;
    const int sel = lane >> 3;
    const int rowq = wid * 16 + l8 + ((sel & 1) << 3);
    const int kcq  = (sel >> 1) << 2;
    const int kck  = (sel & 1) << 2;
    const uint32_t q_base = smem_u32(Qs) + (uint32_t)((rowq * LDQ + kcq) * 4);
    const uint32_t p_base = smem_u32(Ps) + (uint32_t)((rowq * LDP + kcq) * 4);
    uint32_t k_base[4];
    #pragma unroll
    for (int j = 0; j < 4; j++) {
        int rowk = j * 16 + l8 + ((sel >> 1) << 3);
        k_base[j] = smem_u32(Ks) + (uint32_t)((rowk * LDK + kck) * 4);
    }

    const size_t rs = QKVDIM;
    const float* Qg = qkv + (size_t)b * SEQ * rs + h * HDIM;
    const float* Kg = Qg + D_MODEL;
    const float* Vg = Qg + 2 * D_MODEL;

    #pragma unroll
    for (int it = 0; it < 8; it++) {
        int idx = tid + it * 256;
        int rr  = idx >> 4;
        int d0  = (idx & 15) << 2;
        float4 q4 = *(const float4*)(Qg + (size_t)(q0 + rr) * rs + d0);
        *(float4*)&Qs[rr * LDQ + d0] = make_float4(
            f2tff(q4.x * 0.125f), f2tff(q4.y * 0.125f),
            f2tff(q4.z * 0.125f), f2tff(q4.w * 0.125f));
    }

    float m_lo = -1e30f, m_hi = -1e30f, l_lo = 0.f, l_hi = 0.f;
    float o[8][4];
    #pragma unroll
    for (int nt = 0; nt < 8; nt++)
        #pragma unroll
        for (int e = 0; e < 4; e++) o[nt][e] = 0.f;

    const int nkt = 2 * qt + 2;
    for (int kt = 0; kt < nkt; kt++) {
        const int k0 = kt * 64;
        __syncthreads();
        #pragma unroll
        for (int it = 0; it < 4; it++) {
            int idx = tid + it * 256;
            int rr  = idx >> 4;
            int d0  = (idx & 15) << 2;
            float4 k4 = *(const float4*)(Kg + (size_t)(k0 + rr) * rs + d0);
            *(float4*)&Ks[rr * LDK + d0] = make_float4(
                f2tff(k4.x), f2tff(k4.y), f2tff(k4.z), f2tff(k4.w));
            float4 v4 = *(const float4*)(Vg + (size_t)(k0 + rr) * rs + d0);
            *(float4*)&Vs[rr * LDV + d0] = make_float4(
                f2tff(v4.x), f2tff(v4.y), f2tff(v4.z), f2tff(v4.w));
        }
        __syncthreads();

        if (k0 > q0 + wid * 16 + 15) continue;

        // ---- S = Q K^T ----
        float s[8][4];
        #pragma unroll
        for (int nt = 0; nt < 8; nt++)
            #pragma unroll
            for (int e = 0; e < 4; e++) s[nt][e] = 0.f;

        #pragma unroll
        for (int ks = 0; ks < 8; ks++) {
            uint32_t a0, a1, a2, a3;
            ldmx4(a0, a1, a2, a3, q_base + (uint32_t)(ks * 32));
            #pragma unroll
            for (int j = 0; j < 4; j++) {
                uint32_t b00, b01, b10, b11;
                ldmx4(b00, b01, b10, b11, k_base[j] + (uint32_t)(ks * 32));
                mma8(s[2*j][0], s[2*j][1], s[2*j][2], s[2*j][3],
                     a0, a1, a2, a3, b00, b01);
                mma8(s[2*j+1][0], s[2*j+1][1], s[2*j+1][2], s[2*j+1][3],
                     a0, a1, a2, a3, b10, b11);
            }
        }

        const int rglo = q0 + rl;
        const int rghi = rglo + 8;
        if (k0 + 63 > rglo) {
            #pragma unroll
            for (int nt = 0; nt < 8; nt++) {
                int key = k0 + nt * 8 + 2 * ct;
                if (key     > rglo) s[nt][0] = -1e30f;
                if (key + 1 > rglo) s[nt][1] = -1e30f;
                if (key     > rghi) s[nt][2] = -1e30f;
                if (key + 1 > rghi) s[nt][3] = -1e30f;
            }
        }

        float tlo = -1e30f, thi = -1e30f;
        #pragma unroll
        for (int nt = 0; nt < 8; nt++) {
            tlo = fmaxf(tlo, fmaxf(s[nt][0], s[nt][1]));
            thi = fmaxf(thi, fmaxf(s[nt][2], s[nt][3]));
        }
        tlo = fmaxf(tlo, __shfl_xor_sync(0xffffffffu, tlo, 1));
        tlo = fmaxf(tlo, __shfl_xor_sync(0xffffffffu, tlo, 2));
        thi = fmaxf(thi, __shfl_xor_sync(0xffffffffu, thi, 1));
        thi = fmaxf(thi, __shfl_xor_sync(0xffffffffu, thi, 2));

        float mn_lo = fmaxf(m_lo, tlo);
        float mn_hi = fmaxf(m_hi, thi);
        float al_lo = __expf(m_lo - mn_lo);
        float al_hi = __expf(m_hi - mn_hi);
        m_lo = mn_lo; m_hi = mn_hi;

        float ps_lo = 0.f, ps_hi = 0.f;
        #pragma unroll
        for (int nt = 0; nt < 8; nt++) {
            float p0 = __expf(s[nt][0] - mn_lo);
            float p1 = __expf(s[nt][1] - mn_lo);
            float p2 = __expf(s[nt][2] - mn_hi);
            float p3 = __expf(s[nt][3] - mn_hi);
            ps_lo += p0 + p1;
            ps_hi += p2 + p3;
            int col = nt * 8 + 2 * ct;
            *(float2*)&Ps[rl * LDP + col]       = make_float2(f2tff(p0), f2tff(p1));
            *(float2*)&Ps[(rl + 8) * LDP + col] = make_float2(f2tff(p2), f2tff(p3));
        }
        ps_lo += __shfl_xor_sync(0xffffffffu, ps_lo, 1);
        ps_lo += __shfl_xor_sync(0xffffffffu, ps_lo, 2);
        ps_hi += __shfl_xor_sync(0xffffffffu, ps_hi, 1);
        ps_hi += __shfl_xor_sync(0xffffffffu, ps_hi, 2);
        l_lo = l_lo * al_lo + ps_lo;
        l_hi = l_hi * al_hi + ps_hi;

        #pragma unroll
        for (int nt = 0; nt < 8; nt++) {
            o[nt][0] *= al_lo; o[nt][1] *= al_lo;
            o[nt][2] *= al_hi; o[nt][3] *= al_hi;
        }
        __syncwarp();

        // ---- O += P V ----
        #pragma unroll
        for (int ks = 0; ks < 8; ks++) {
            uint32_t a0, a1, a2, a3;
            ldmx4(a0, a1, a2, a3, p_base + (uint32_t)(ks * 32));
            #pragma unroll
            for (int nt = 0; nt < 8; nt++) {
                uint32_t b0 = Vu[(ks * 8 + ct) * LDV + nt * 8 + g];
                uint32_t b1 = Vu[(ks * 8 + ct + 4) * LDV + nt * 8 + g];
                mma8(o[nt][0], o[nt][1], o[nt][2], o[nt][3], a0, a1, a2, a3, b0, b1);
            }
        }
    }

    float inv_lo = 1.0f / l_lo;
    float inv_hi = 1.0f / l_hi;
    float* Og = attn_out + (size_t)(b * SEQ + q0) * D_MODEL + h * HDIM;
    #pragma unroll
    for (int nt = 0; nt < 8; nt++) {
        int col = nt * 8 + 2 * ct;
        *(float2*)&Og[(size_t)rl * D_MODEL + col] =
            make_float2(o[nt][0] * inv_lo, o[nt][1] * inv_lo);
        *(float2*)&Og[(size_t)(rl + 8) * D_MODEL + col] =
            make_float2(o[nt][2] * inv_hi, o[nt][3] * inv_hi);
    }
}

// ===========================================================================
extern "C" void kernel_launch(void* const* d_in, const int* in_sizes, int n_in,
                              void* d_out, int out_size)
{
    const float* x      = (const float*)d_in[0];
    const float* w_qkv  = (const float*)d_in[1];
    const float* w_proj = (const float*)d_in[2];
    float* out = (float*)d_out;

    float *qkv, *attn;
    cudaGetSymbolAddress((void**)&qkv,  g_qkv);
    cudaGetSymbolAddress((void**)&attn, g_attn);

    cudaFuncSetAttribute(gemm_tf32,
                         cudaFuncAttributeMaxDynamicSharedMemorySize, GEMM_SMEM);
    cudaFuncSetAttribute(attn_mma,
                         cudaFuncAttributeMaxDynamicSharedMemorySize, ATTN_SMEM);

    // 1) QKV projection
    dim3 g1(QKVDIM/128, MROWS/128);
    gemm_tf32<<<g1, 512, GEMM_SMEM>>>(x, w_qkv, qkv, MROWS, QKVDIM, D_MODEL);

    // 2) causal flash attention (tf32 mma)
    dim3 g2(SEQ/128, NHEAD, BATCH);
    attn_mma<<<g2, 256, ATTN_SMEM>>>(qkv, attn);

    // 3) output projection
    dim3 g3(D_MODEL/128, MROWS/128);
    gemm_tf32<<<g3, 512, GEMM_SMEM>>>(attn, w_proj, out, MROWS, D_MODEL, D_MODEL);
}